// round 7
// baseline (speedup 1.0000x reference)
#include <cuda_runtime.h>
#include <math.h>

#define NP 8732
#define NG 20
#define NC 21
#define NB 128
#define TPB 256
#define NT_L 35            // lse tiles of 256 priors (34*256 + 28)
#define NT_M 3             // match tiles
#define MTW 2911           // priors per match tile (last tile = 2910)
#define PPT 12             // ceil(2911/256)
#define NT_TOT (NT_L + NT_M)
#define PER2 35            // finalize: ceil(8732/256)
#define NWARP 8

__device__ float g_ce0[(size_t)NB * NP];            // lse - conf[...,0]
__device__ float g_iou[(size_t)NB * NP];            // per-prior best IoU
__device__ unsigned char g_bidx[(size_t)NB * NP];   // per-prior best GT idx
__device__ unsigned long long g_bestp[NB * NG];     // packed (iou_bits<<32)|~p
__device__ unsigned g_tick[NB];                     // per-batch arrival ticket
__device__ float g_pl[NB], g_pc[NB];
__device__ int g_pn[NB];
__device__ unsigned g_done;

__device__ __forceinline__ float warpSumF(float v) {
  #pragma unroll
  for (int o = 16; o > 0; o >>= 1) v += __shfl_down_sync(0xffffffffu, v, o);
  return v;
}
__device__ __forceinline__ float sl1(float x) {
  float a = fabsf(x);
  return a < 1.f ? 0.5f * x * x : a - 0.5f;
}

union SmemU {                      // phases are strictly sequential per block
  float tile[TPB * NC];            // lse staging: 21504 B
  struct {                         // match phase
    float4 g4[NG]; float ga[NG];
    unsigned long long pk[NG];     // per-block racing max per GT
  } m;
  struct {                         // finalize phase (written after flag sync)
    float4 g4[NG]; int glab[NG]; unsigned fp[NG];
  } f;
};

__global__ void __launch_bounds__(TPB, 3)
ssd_kernel(const float* __restrict__ loc, const float* __restrict__ conf,
           const float* __restrict__ dbox, const float* __restrict__ gtb,
           const int* __restrict__ gtl, float* __restrict__ out)
{
  __shared__ SmemU s;
  __shared__ int s_flag1, s_flag2;          // outside union: no aliasing races
  __shared__ int s_redi[NWARP];
  __shared__ float s_redf[3][NWARP];

  const int bid = blockIdx.x;
  const int b   = bid / NT_TOT;
  const int r   = bid - b * NT_TOT;
  const int tid = threadIdx.x;
  const int wi  = tid >> 5, li = tid & 31;

  if (r < NT_L) {
    // ================= LSE tile: ce0 = lse(conf row) - conf[...,0] =========
    const int p0  = r * TPB;
    const int cnt = min(TPB, NP - p0);
    const int nf4 = cnt * NC / 4;           // 256*21, 28*21 both %4==0
    const float4* src = (const float4*)(conf + ((size_t)b * NP + p0) * NC);
    float4* dst = (float4*)s.tile;
    for (int i = tid; i < nf4; i += TPB) dst[i] = src[i];
    __syncthreads();
    if (tid < cnt) {
      const float* row = s.tile + tid * NC;   // stride 21: conflict-free
      float s0 = 0.f, s1 = 0.f, s2 = 0.f;
      #pragma unroll
      for (int k = 0; k < 21; k += 3) {
        s0 += __expf(row[k]);
        s1 += __expf(row[k + 1]);
        s2 += __expf(row[k + 2]);
      }
      g_ce0[(size_t)b * NP + p0 + tid] = __logf(s0 + s1 + s2) - row[0];
    }
  } else {
    // ================= Match tile: IoU, both argmaxes ======================
    const int base = (r - NT_L) * MTW;
    const int pend = min(base + MTW, NP);
    if (tid < NG) {
      float4 g = ((const float4*)gtb)[b * NG + tid];
      s.m.g4[tid] = g;
      s.m.ga[tid] = (g.z - g.x) * (g.w - g.y);
      s.m.pk[tid] = 0ull;
    }
    __syncthreads();
    #pragma unroll
    for (int i = 0; i < PPT; i++) {
      int p = base + tid + i * TPB;
      if (p < pend) {
        float4 d = ((const float4*)dbox)[p];  // cx,cy,w,h
        float hx = 0.5f * d.z, hy = 0.5f * d.w;
        float ax0 = d.x - hx, ay0 = d.y - hy, ax1 = d.x + hx, ay1 = d.y + hy;
        float areaA = d.z * d.w;
        float best = 0.f; int bi = 0;         // all-zero row -> idx 0 (JAX)
        #pragma unroll
        for (int j = 0; j < NG; j++) {
          float4 g = s.m.g4[j];
          float w = fminf(ax1, g.z) - fmaxf(ax0, g.x);
          float h = fminf(ay1, g.w) - fmaxf(ay0, g.y);
          float inter = fmaxf(w, 0.f) * fmaxf(h, 0.f);
          float den = (areaA + s.m.ga[j]) - inter;
          float iou = __fdividef(inter, den);
          if (iou > best) { best = iou; bi = j; }   // strict >: FIRST max (axis=1)
          unsigned bits = __float_as_uint(iou);     // iou>=0: order-preserving
          // racing monotone max: stale read only causes a redundant atomic
          unsigned hiw = ((volatile unsigned*)&s.m.pk[j])[1];
          if (bits >= hiw)
            atomicMax(&s.m.pk[j],
                      ((unsigned long long)bits << 32) |
                      (0xFFFFFFFFu - (unsigned)p));
        }
        g_iou[(size_t)b * NP + p]  = best;
        g_bidx[(size_t)b * NP + p] = (unsigned char)bi;
      }
    }
    __syncthreads();
    if (tid < NG) atomicMax(&g_bestp[b * NG + tid], s.m.pk[tid]);
  }

  // ================= Per-batch ticket: last block finalizes =================
  __threadfence();
  if (tid == 0) {
    unsigned old = atomicAdd(&g_tick[b], 1u);       // modular: replay-safe
    s_flag1 = ((old % NT_TOT) == NT_TOT - 1);
  }
  __syncthreads();
  if (!s_flag1) return;

  // ---- Finalize batch b (256 threads) ----
  if (tid < NG) {
    float4 g = ((const float4*)gtb)[b * NG + tid];
    s.f.g4[tid]   = g;
    s.f.glab[tid] = gtl[b * NG + tid];
    unsigned long long bp = g_bestp[b * NG + tid];  // never 0: >= always fires
    s.f.fp[tid] = 0xFFFFFFFFu - (unsigned)(bp & 0xFFFFFFFFull);
  }
  __syncthreads();
  // Forced matches: sequential last-write-wins (JAX scatter order), straight
  // to gmem; same-block coherence via __syncthreads.
  if (tid == 0) {
    #pragma unroll
    for (int j = 0; j < NG; j++) {
      unsigned p = s.f.fp[j];
      g_iou[(size_t)b * NP + p]  = 2.f;
      g_bidx[(size_t)b * NP + p] = (unsigned char)j;
    }
  }
  __syncthreads();

  // ---- Phase B: losses; loss_c in registers ----
  float th_loc = 0.f, th_pce = 0.f; int th_np = 0;
  unsigned lcr[PER2];
  #pragma unroll
  for (int i = 0; i < PER2; i++) {
    int p = tid + i * TPB;
    unsigned v = 0u;
    if (p < NP) {
      float biou = g_iou[(size_t)b * NP + p];
      int j = g_bidx[(size_t)b * NP + p];
      float ce0 = g_ce0[(size_t)b * NP + p];
      if (biou > 0.5f) {                    // pos (gt labels all >= 1)
        int lab = s.f.glab[j];
        const float* cp = conf + ((size_t)b * NP + p) * NC;
        float c0 = __ldg(cp), cl = __ldg(cp + lab);
        th_pce += ce0 + c0 - cl;            // ce = lse - conf[lab]
        th_np++;
        float4 d = ((const float4*)dbox)[p];
        float4 g = s.f.g4[j];
        float e0 = ((g.x + g.z) * 0.5f - d.x) / (0.1f * d.z);
        float e1 = ((g.y + g.w) * 0.5f - d.y) / (0.1f * d.w);
        float e2 = __logf((g.z - g.x) / d.z) * 5.f;
        float e3 = __logf((g.w - g.y) / d.w) * 5.f;
        float4 L = ((const float4*)loc)[(size_t)b * NP + p];
        th_loc += sl1(L.x - e0) + sl1(L.y - e1) + sl1(L.z - e2) + sl1(L.w - e3);
      } else {
        v = __float_as_uint(ce0);           // ce0 > 0: bits order-preserving
      }
    }
    lcr[i] = v;
  }

  {
    float a = warpSumF(th_loc), c = warpSumF(th_pce);
    int n = (int)__reduce_add_sync(0xffffffffu, (unsigned)th_np);
    if (li == 0) { s_redf[0][wi] = a; s_redf[1][wi] = c; s_redi[wi] = n; }
  }
  __syncthreads();
  float locl = 0.f, pce = 0.f; int npos = 0;
  #pragma unroll
  for (int w = 0; w < NWARP; w++) {
    locl += s_redf[0][w]; pce += s_redf[1][w]; npos += s_redi[w];
  }
  int k = min(3 * npos, NP - npos);

  // ---- Phase C: top-k sum via binary search on float bit patterns ----
  float topk = 0.f;
  if (k > 0) {
    unsigned lo = 0u, hi = 0x7F800000u;
    while (lo < hi) {
      unsigned mid = (lo + hi) >> 1;
      unsigned c = 0;
      #pragma unroll
      for (int i = 0; i < PER2; i++) c += (lcr[i] > mid);
      c = __reduce_add_sync(0xffffffffu, c);
      __syncthreads();                      // protect s_redi reuse
      if (li == 0) s_redi[wi] = (int)c;
      __syncthreads();
      int tot = 0;
      #pragma unroll
      for (int w = 0; w < NWARP; w++) tot += s_redi[w];
      if (tot < k) hi = mid; else lo = mid + 1u;   // uniform across block
    }
    int m = 0; float sg = 0.f;
    #pragma unroll
    for (int i = 0; i < PER2; i++) {
      unsigned u = lcr[i];
      if (u > lo) { m++; sg += __uint_as_float(u); }
    }
    m = (int)__reduce_add_sync(0xffffffffu, (unsigned)m);
    sg = warpSumF(sg);
    __syncthreads();
    if (li == 0) { s_redi[wi] = m; s_redf[2][wi] = sg; }
    __syncthreads();
    int mt = 0; float sgt = 0.f;
    #pragma unroll
    for (int w = 0; w < NWARP; w++) { mt += s_redi[w]; sgt += s_redf[2][w]; }
    topk = sgt + (float)(k - mt) * __uint_as_float(lo);
  }

  // ---- Publish partials; globally-last finalizer reduces and writes out ----
  if (tid == 0) {
    g_pl[b] = locl;
    g_pc[b] = pce + topk;
    g_pn[b] = npos;
  }
  __threadfence();
  __syncthreads();
  if (tid == 0) {
    unsigned od = atomicAdd(&g_done, 1u);   // modular: replay-safe
    s_flag2 = ((od % NB) == NB - 1);
  }
  __syncthreads();
  if (s_flag2) {
    float L = 0.f, C = 0.f; int n = 0;
    if (tid < NB) {
      L = ((volatile float*)g_pl)[tid];
      C = ((volatile float*)g_pc)[tid];
      n = ((volatile int*)g_pn)[tid];
    }
    L = warpSumF(L); C = warpSumF(C);
    n = (int)__reduce_add_sync(0xffffffffu, (unsigned)n);
    __syncthreads();
    if (li == 0) { s_redf[0][wi] = L; s_redf[1][wi] = C; s_redi[wi] = n; }
    __syncthreads();
    if (tid == 0) {
      float Lt = 0.f, Ct = 0.f; int nt = 0;
      #pragma unroll
      for (int w = 0; w < NWARP; w++) {
        Lt += s_redf[0][w]; Ct += s_redf[1][w]; nt += s_redi[w];
      }
      out[0] = (Lt + Ct) / (float)max(nt, 1);
    }
  }
}

extern "C" void kernel_launch(void* const* d_in, const int* in_sizes, int n_in,
                              void* d_out, int out_size) {
  const float* loc  = (const float*)d_in[0];
  const float* conf = (const float*)d_in[1];
  const float* dbox = (const float*)d_in[2];
  const float* gtb  = (const float*)d_in[3];
  const int*   gtl  = (const int*)d_in[4];
  float* out = (float*)d_out;

  ssd_kernel<<<NB * NT_TOT, TPB>>>(loc, conf, dbox, gtb, gtl, out);
}

// round 8
// speedup vs baseline: 1.0889x; 1.0889x over previous
#include <cuda_runtime.h>
#include <math.h>

#define NP 8732
#define NG 20
#define NC 21
#define NB 128
#define TPB 512
#define NT_L 18            // lse tiles of 512 priors (17*512 + 28)
#define NT_M 6             // match tiles
#define CH 3               // prior chunks per match block
#define MBP (TPB*CH)       // 1536 priors per match block (6*1536 >= 8732)
#define NT_TOT (NT_L + NT_M)
#define PERF 18            // finalize: ceil(8732/512)
#define NWARP 16

__device__ float g_ce0[(size_t)NB * NP];            // lse - conf[...,0]
__device__ float g_iou[(size_t)NB * NP];            // per-prior best IoU
__device__ unsigned char g_bidx[(size_t)NB * NP];   // per-prior best GT idx
__device__ unsigned long long g_bestp[NB * NG];     // packed (iou_bits<<32)|~p
__device__ unsigned g_tick[NB];                     // per-batch arrival ticket
__device__ float g_pl[NB], g_pc[NB];
__device__ int g_pn[NB];
__device__ unsigned g_done;

__device__ __forceinline__ float warpSumF(float v) {
  #pragma unroll
  for (int o = 16; o > 0; o >>= 1) v += __shfl_down_sync(0xffffffffu, v, o);
  return v;
}
__device__ __forceinline__ float sl1(float x) {
  float a = fabsf(x);
  return a < 1.f ? 0.5f * x * x : a - 0.5f;
}

union SmemU {                      // phases strictly sequential per block
  float tile[TPB * NC];            // lse staging: 43008 B
  struct { float4 g4[NG]; float ga[NG]; } m;              // match phase
  struct { float4 g4[NG]; int glab[NG]; unsigned fp[NG]; } f;  // finalize
};

__global__ void __launch_bounds__(TPB, 2)
ssd_kernel(const float* __restrict__ loc, const float* __restrict__ conf,
           const float* __restrict__ dbox, const float* __restrict__ gtb,
           const int* __restrict__ gtl, float* __restrict__ out)
{
  __shared__ SmemU s;
  __shared__ int s_flag1, s_flag2;
  __shared__ int s_redi[NWARP];
  __shared__ float s_redf[3][NWARP];
  __shared__ int s_toti; __shared__ float s_totf;

  const int bid = blockIdx.x;
  const int b   = bid / NT_TOT;
  const int r   = bid - b * NT_TOT;
  const int tid = threadIdx.x;
  const int wi  = tid >> 5, li = tid & 31;
  const size_t bofs = (size_t)b * NP;

  if (r < NT_L) {
    // ================= LSE tile: ce0 = lse(conf row) - conf[...,0] =========
    const int p0  = r * TPB;
    const int cnt = min(TPB, NP - p0);
    const int nf4 = cnt * NC / 4;           // 512*21, 28*21 both %4==0
    const float4* src = (const float4*)(conf + (bofs + p0) * NC);
    float4* dst = (float4*)s.tile;
    for (int i = tid; i < nf4; i += TPB) dst[i] = src[i];
    __syncthreads();
    if (tid < cnt) {
      const float* row = s.tile + tid * NC;   // stride 21: conflict-free
      float s0 = 0.f, s1 = 0.f, s2 = 0.f;
      #pragma unroll
      for (int k = 0; k < 21; k += 3) {
        s0 += __expf(row[k]);
        s1 += __expf(row[k + 1]);
        s2 += __expf(row[k + 2]);
      }
      g_ce0[bofs + p0 + tid] = __logf(s0 + s1 + s2) - row[0];
    }
  } else {
    // ================= Match tile: branchless IoU + both argmaxes ==========
    const int mb = r - NT_L;
    if (tid < NG) {
      float4 g = ((const float4*)gtb)[b * NG + tid];
      s.m.g4[tid] = g;
      s.m.ga[tid] = (g.z - g.x) * (g.w - g.y);
    }
    __syncthreads();
    unsigned long long acc = 0ull;          // lane j: running (bits<<32)|~p
    #pragma unroll
    for (int c = 0; c < CH; c++) {
      const int plin  = mb * MBP + c * TPB + tid;
      const int pv    = min(plin, NP - 1);
      const bool valid = plin < NP;
      const unsigned wbase = (unsigned)(mb * MBP + c * TPB + (tid & ~31));
      float4 d = ((const float4*)dbox)[pv];  // cx,cy,w,h
      float ax0 = fmaf(-0.5f, d.z, d.x), ax1 = fmaf(0.5f, d.z, d.x);
      float ay0 = fmaf(-0.5f, d.w, d.y), ay1 = fmaf(0.5f, d.w, d.y);
      float areaA = d.z * d.w;
      unsigned bb = 0u; int bi = 0;          // all-zero row -> idx 0 (JAX)
      #pragma unroll
      for (int j = 0; j < NG; j++) {
        float4 g = s.m.g4[j];
        float w = fminf(ax1, g.z) - fmaxf(ax0, g.x);
        float h = fminf(ay1, g.w) - fmaxf(ay0, g.y);
        float inter = fmaxf(w, 0.f) * fmaxf(h, 0.f);
        float iou = __fdividef(inter, (areaA + s.m.ga[j]) - inter);
        unsigned bits = __float_as_uint(iou);  // iou>=0: order-preserving
        bool gq = bits > bb;                   // strict >: FIRST max (axis=1)
        bb = gq ? bits : bb;
        bi = gq ? j : bi;
        // axis=0 argmax: warp collective, fully branchless
        unsigned rb = valid ? bits : 0u;       // zeroed dup lanes never win:
        unsigned mx = __reduce_max_sync(0xffffffffu, rb);   // their ~p is
        unsigned em = __ballot_sync(0xffffffffu, rb == mx); // strictly smaller
        unsigned wl = (unsigned)(__ffs(em) - 1);  // lowest lane = smallest p
        unsigned long long pk = ((unsigned long long)mx << 32)
                              | (0xFFFFFFFFu - (wbase + wl));
        bool tk = (li == j) & (pk > acc);
        acc = tk ? pk : acc;
      }
      if (valid) {
        g_iou[bofs + plin]  = __uint_as_float(bb);
        g_bidx[bofs + plin] = (unsigned char)bi;
      }
    }
    if (li < NG) atomicMax(&g_bestp[b * NG + li], acc);  // once per warp
  }

  // ================= Per-batch ticket: last block finalizes =================
  __threadfence();
  if (tid == 0) {
    unsigned old = atomicAdd(&g_tick[b], 1u);       // modular: replay-safe
    s_flag1 = ((old % NT_TOT) == NT_TOT - 1);
  }
  __syncthreads();
  if (!s_flag1) return;
  __threadfence();                                   // acquire batch data

  // ---- Finalize batch b ----
  if (tid < NG) {
    float4 g = ((const float4*)gtb)[b * NG + tid];
    s.f.g4[tid]   = g;
    s.f.glab[tid] = gtl[b * NG + tid];
    unsigned long long bp = g_bestp[b * NG + tid];  // never 0 (always fired)
    s.f.fp[tid] = 0xFFFFFFFFu - (unsigned)(bp & 0xFFFFFFFFull);
  }
  __syncthreads();
  // Forced matches: sequential last-write-wins (JAX scatter order)
  if (tid == 0) {
    #pragma unroll
    for (int j = 0; j < NG; j++) {
      unsigned p = s.f.fp[j];
      g_iou[bofs + p]  = 2.f;
      g_bidx[bofs + p] = (unsigned char)j;
    }
  }
  __syncthreads();

  // ---- Phase B: losses; loss_c in registers ----
  float th_loc = 0.f, th_pce = 0.f; int th_np = 0;
  unsigned lcr[PERF];
  #pragma unroll
  for (int i = 0; i < PERF; i++) {
    int p = tid + i * TPB;
    unsigned v = 0u;
    if (p < NP) {
      float biou = g_iou[bofs + p];
      int j = g_bidx[bofs + p];
      float ce0 = g_ce0[bofs + p];
      if (biou > 0.5f) {                    // pos (gt labels all >= 1)
        int lab = s.f.glab[j];
        const float* cp = conf + (bofs + p) * NC;
        float c0 = __ldg(cp), cl = __ldg(cp + lab);
        th_pce += ce0 + c0 - cl;            // ce = lse - conf[lab]
        th_np++;
        float4 d = ((const float4*)dbox)[p];
        float4 g = s.f.g4[j];
        float e0 = ((g.x + g.z) * 0.5f - d.x) / (0.1f * d.z);
        float e1 = ((g.y + g.w) * 0.5f - d.y) / (0.1f * d.w);
        float e2 = __logf((g.z - g.x) / d.z) * 5.f;
        float e3 = __logf((g.w - g.y) / d.w) * 5.f;
        float4 L = ((const float4*)loc)[bofs + p];
        th_loc += sl1(L.x - e0) + sl1(L.y - e1) + sl1(L.z - e2) + sl1(L.w - e3);
      } else {
        v = __float_as_uint(ce0);           // ce0 > 0: bits order-preserving
      }
    }
    lcr[i] = v;
  }

  {
    float a = warpSumF(th_loc), c = warpSumF(th_pce);
    int n = (int)__reduce_add_sync(0xffffffffu, (unsigned)th_np);
    if (li == 0) { s_redf[0][wi] = a; s_redf[1][wi] = c; s_redi[wi] = n; }
  }
  __syncthreads();
  float locl = 0.f, pce = 0.f; int npos = 0;
  #pragma unroll
  for (int w = 0; w < NWARP; w++) {
    locl += s_redf[0][w]; pce += s_redf[1][w]; npos += s_redi[w];
  }
  int k = min(3 * npos, NP - npos);

  // ---- Phase C: top-k sum via binary search on float bit patterns ----
  float topk = 0.f;
  if (k > 0) {
    unsigned lo = 0u, hi = 0x7F800000u;
    while (lo < hi) {
      unsigned mid = (lo + hi) >> 1;
      unsigned c = 0;
      #pragma unroll
      for (int i = 0; i < PERF; i++) c += (lcr[i] > mid);
      c = __reduce_add_sync(0xffffffffu, c);
      if (li == 0) s_redi[wi] = (int)c;
      __syncthreads();
      if (wi == 0) {                         // warp0 combines 16 partials
        int t = (li < NWARP) ? s_redi[li] : 0;
        t = (int)__reduce_add_sync(0xffffffffu, (unsigned)t);
        if (li == 0) s_toti = t;
      }
      __syncthreads();
      if (s_toti < k) hi = mid; else lo = mid + 1u;  // uniform across block
    }
    int m = 0; float sg = 0.f;
    #pragma unroll
    for (int i = 0; i < PERF; i++) {
      unsigned u = lcr[i];
      if (u > lo) { m++; sg += __uint_as_float(u); }
    }
    m = (int)__reduce_add_sync(0xffffffffu, (unsigned)m);
    sg = warpSumF(sg);
    if (li == 0) { s_redi[wi] = m; s_redf[2][wi] = sg; }
    __syncthreads();
    if (wi == 0) {
      int mt = (li < NWARP) ? s_redi[li] : 0;
      float st = (li < NWARP) ? s_redf[2][li] : 0.f;
      mt = (int)__reduce_add_sync(0xffffffffu, (unsigned)mt);
      st = warpSumF(st);
      if (li == 0) {
        s_toti = mt; s_totf = st;
      }
    }
    __syncthreads();
    topk = s_totf + (float)(k - s_toti) * __uint_as_float(lo);
  }

  // ---- Publish partials; globally-last finalizer writes out ----
  if (tid == 0) {
    g_pl[b] = locl;
    g_pc[b] = pce + topk;
    g_pn[b] = npos;
  }
  __threadfence();
  __syncthreads();
  if (tid == 0) {
    unsigned od = atomicAdd(&g_done, 1u);   // modular: replay-safe
    s_flag2 = ((od % NB) == NB - 1);
  }
  __syncthreads();
  if (s_flag2) {
    __threadfence();
    float L = 0.f, C = 0.f; int n = 0;
    if (tid < NB) {
      L = ((volatile float*)g_pl)[tid];
      C = ((volatile float*)g_pc)[tid];
      n = ((volatile int*)g_pn)[tid];
    }
    L = warpSumF(L); C = warpSumF(C);
    n = (int)__reduce_add_sync(0xffffffffu, (unsigned)n);
    if (li == 0) { s_redf[0][wi] = L; s_redf[1][wi] = C; s_redi[wi] = n; }
    __syncthreads();
    if (tid == 0) {
      float Lt = 0.f, Ct = 0.f; int nt = 0;
      #pragma unroll
      for (int w = 0; w < NWARP; w++) {
        Lt += s_redf[0][w]; Ct += s_redf[1][w]; nt += s_redi[w];
      }
      out[0] = (Lt + Ct) / (float)max(nt, 1);
    }
  }
}

extern "C" void kernel_launch(void* const* d_in, const int* in_sizes, int n_in,
                              void* d_out, int out_size) {
  const float* loc  = (const float*)d_in[0];
  const float* conf = (const float*)d_in[1];
  const float* dbox = (const float*)d_in[2];
  const float* gtb  = (const float*)d_in[3];
  const int*   gtl  = (const int*)d_in[4];
  float* out = (float*)d_out;

  ssd_kernel<<<NB * NT_TOT, TPB>>>(loc, conf, dbox, gtb, gtl, out);
}

// round 9
// speedup vs baseline: 1.3087x; 1.2018x over previous
#include <cuda_runtime.h>
#include <math.h>

#define NP 8732
#define NG 20
#define NC 21
#define NB 128
#define TPB 512
#define NT_L 18            // lse tiles of 512 priors (17*512 + 28)
#define NT_M 6             // match tiles
#define CH 3               // priors per thread (register-resident)
#define MBP (TPB*CH)       // 1536 priors per match block (6*1536 >= 8732)
#define NT_TOT (NT_L + NT_M)
#define PERF 18            // finalize: ceil(8732/512)
#define NWARP 16

__device__ float g_ce0[(size_t)NB * NP];            // lse - conf[...,0]
__device__ float g_iou[(size_t)NB * NP];            // per-prior best IoU
__device__ unsigned char g_bidx[(size_t)NB * NP];   // per-prior best GT idx
__device__ unsigned long long g_bestp[NB * NG];     // packed (iou_bits<<32)|~p
__device__ unsigned g_tick[NB];                     // per-batch arrival ticket
__device__ float g_pl[NB], g_pc[NB];
__device__ int g_pn[NB];
__device__ unsigned g_done;

__device__ __forceinline__ float warpSumF(float v) {
  #pragma unroll
  for (int o = 16; o > 0; o >>= 1) v += __shfl_down_sync(0xffffffffu, v, o);
  return v;
}
__device__ __forceinline__ float sl1(float x) {
  float a = fabsf(x);
  return a < 1.f ? 0.5f * x * x : a - 0.5f;
}

union SmemU {                      // phases strictly sequential per block
  float tile[TPB * NC];            // lse staging: 43008 B
  struct { float4 g4[NG]; float ga[NG]; } m;              // match phase
  struct { float4 g4[NG]; int glab[NG]; unsigned fp[NG]; } f;  // finalize
};

__global__ void __launch_bounds__(TPB, 2)
ssd_kernel(const float* __restrict__ loc, const float* __restrict__ conf,
           const float* __restrict__ dbox, const float* __restrict__ gtb,
           const int* __restrict__ gtl, float* __restrict__ out)
{
  __shared__ SmemU s;
  __shared__ int s_flag1, s_flag2;
  __shared__ int s_redi[NWARP];
  __shared__ float s_redf[3][NWARP];
  __shared__ int s_toti; __shared__ float s_totf;

  const int bid = blockIdx.x;
  const int b   = bid / NT_TOT;
  const int r   = bid - b * NT_TOT;
  const int tid = threadIdx.x;
  const int wi  = tid >> 5, li = tid & 31;
  const size_t bofs = (size_t)b * NP;

  if (r < NT_L) {
    // ================= LSE tile: ce0 = lse(conf row) - conf[...,0] =========
    const int p0  = r * TPB;
    const int cnt = min(TPB, NP - p0);
    const int nf4 = cnt * NC / 4;           // 512*21, 28*21 both %4==0
    const float4* src = (const float4*)(conf + (bofs + p0) * NC);
    float4* dst = (float4*)s.tile;
    for (int i = tid; i < nf4; i += TPB) dst[i] = src[i];
    __syncthreads();
    if (tid < cnt) {
      const float* row = s.tile + tid * NC;   // stride 21: conflict-free
      float s0 = 0.f, s1 = 0.f, s2 = 0.f;
      #pragma unroll
      for (int k = 0; k < 21; k += 3) {
        s0 += __expf(row[k]);
        s1 += __expf(row[k + 1]);
        s2 += __expf(row[k + 2]);
      }
      g_ce0[bofs + p0 + tid] = __logf(s0 + s1 + s2) - row[0];
    }
  } else {
    // ========= Match tile: scalar inner loop, per-(warp,GT) collectives ====
    const int mbase = (r - NT_L) * MBP;
    if (tid < NG) {
      float4 g = ((const float4*)gtb)[b * NG + tid];
      s.m.g4[tid] = g;
      s.m.ga[tid] = (g.z - g.x) * (g.w - g.y);
    }
    __syncthreads();

    // CH priors fully register-resident
    float ax0[CH], ay0[CH], ax1[CH], ay1[CH], areaA[CH];
    unsigned pidx[CH]; bool valid[CH];
    #pragma unroll
    for (int i = 0; i < CH; i++) {
      int plin = mbase + i * TPB + tid;
      valid[i] = plin < NP;
      pidx[i]  = (unsigned)plin;
      float4 d = ((const float4*)dbox)[min(plin, NP - 1)];   // cx,cy,w,h
      ax0[i] = fmaf(-0.5f, d.z, d.x); ax1[i] = fmaf(0.5f, d.z, d.x);
      ay0[i] = fmaf(-0.5f, d.w, d.y); ay1[i] = fmaf(0.5f, d.w, d.y);
      areaA[i] = d.z * d.w;
    }
    unsigned bb[CH]; int bi[CH];
    #pragma unroll
    for (int i = 0; i < CH; i++) { bb[i] = 0u; bi[i] = 0; }  // zeros -> idx 0

    unsigned long long acc = 0ull;          // lane j holds pk for GT j
    #pragma unroll
    for (int j = 0; j < NG; j++) {
      float4 g = s.m.g4[j];                 // LDS broadcast
      float ga = s.m.ga[j];
      unsigned tbits = 0u, tp = 0xFFFFFFFFu;  // thread-local argmax for GT j
      #pragma unroll
      for (int i = 0; i < CH; i++) {
        float w = fminf(ax1[i], g.z) - fmaxf(ax0[i], g.x);
        float h = fminf(ay1[i], g.w) - fmaxf(ay0[i], g.y);
        float inter = fmaxf(w, 0.f) * fmaxf(h, 0.f);
        float iou = __fdividef(inter, (areaA[i] + ga) - inter);
        unsigned bits = __float_as_uint(iou);   // iou>=0: order-preserving
        bool gq = bits > bb[i];                 // strict >: FIRST max (axis=1)
        bb[i] = gq ? bits : bb[i];
        bi[i] = gq ? j : bi[i];
        unsigned cb = valid[i] ? bits : 0u;
        bool tq = cb > tbits;                   // strict >: lowest i = lowest p
        tbits = tq ? cb : tbits;
        tp    = tq ? pidx[i] : tp;              // tp sentinel iff tbits==0
      }
      // axis=0 argmax across warp: 2 collectives per (warp, GT)
      unsigned mx = __reduce_max_sync(0xffffffffu, tbits);
      unsigned pc = (tbits == mx) ? tp : 0xFFFFFFFFu;
      unsigned pmin = __reduce_min_sync(0xffffffffu, pc);  // smallest p wins
      // mx==0 -> pmin sentinel -> pk==0 (no contribution)
      unsigned long long pk = ((unsigned long long)mx << 32)
                            | (0xFFFFFFFFu - pmin);
      acc = (li == j) ? pk : acc;             // block sees each j exactly once
    }
    if (li < NG) atomicMax(&g_bestp[b * NG + li], acc);  // merge across blocks
    #pragma unroll
    for (int i = 0; i < CH; i++) {
      if (valid[i]) {
        g_iou[bofs + pidx[i]]  = __uint_as_float(bb[i]);
        g_bidx[bofs + pidx[i]] = (unsigned char)bi[i];
      }
    }
  }

  // ================= Per-batch ticket: last block finalizes =================
  __threadfence();
  if (tid == 0) {
    unsigned old = atomicAdd(&g_tick[b], 1u);       // modular: replay-safe
    s_flag1 = ((old % NT_TOT) == NT_TOT - 1);
  }
  __syncthreads();
  if (!s_flag1) return;
  __threadfence();                                   // acquire batch data

  // ---- Finalize batch b ----
  if (tid < NG) {
    float4 g = ((const float4*)gtb)[b * NG + tid];
    s.f.g4[tid]   = g;
    s.f.glab[tid] = gtl[b * NG + tid];
    unsigned long long bp = g_bestp[b * NG + tid];
    // bp==0 (GT overlapped nothing): argmax-of-zeros -> prior 0 (JAX)
    s.f.fp[tid] = bp ? (0xFFFFFFFFu - (unsigned)(bp & 0xFFFFFFFFull)) : 0u;
  }
  __syncthreads();
  // Forced matches: sequential last-write-wins (JAX scatter order)
  if (tid == 0) {
    #pragma unroll
    for (int j = 0; j < NG; j++) {
      unsigned p = s.f.fp[j];
      g_iou[bofs + p]  = 2.f;
      g_bidx[bofs + p] = (unsigned char)j;
    }
  }
  __syncthreads();

  // ---- Phase B: losses; loss_c in registers ----
  float th_loc = 0.f, th_pce = 0.f; int th_np = 0;
  unsigned lcr[PERF];
  #pragma unroll
  for (int i = 0; i < PERF; i++) {
    int p = tid + i * TPB;
    unsigned v = 0u;
    if (p < NP) {
      float biou = g_iou[bofs + p];
      int j = g_bidx[bofs + p];
      float ce0 = g_ce0[bofs + p];
      if (biou > 0.5f) {                    // pos (gt labels all >= 1)
        int lab = s.f.glab[j];
        const float* cp = conf + (bofs + p) * NC;
        float c0 = __ldg(cp), cl = __ldg(cp + lab);
        th_pce += ce0 + c0 - cl;            // ce = lse - conf[lab]
        th_np++;
        float4 d = ((const float4*)dbox)[p];
        float4 g = s.f.g4[j];
        float e0 = ((g.x + g.z) * 0.5f - d.x) / (0.1f * d.z);
        float e1 = ((g.y + g.w) * 0.5f - d.y) / (0.1f * d.w);
        float e2 = __logf((g.z - g.x) / d.z) * 5.f;
        float e3 = __logf((g.w - g.y) / d.w) * 5.f;
        float4 L = ((const float4*)loc)[bofs + p];
        th_loc += sl1(L.x - e0) + sl1(L.y - e1) + sl1(L.z - e2) + sl1(L.w - e3);
      } else {
        v = __float_as_uint(ce0);           // ce0 > 0: bits order-preserving
      }
    }
    lcr[i] = v;
  }

  {
    float a = warpSumF(th_loc), c = warpSumF(th_pce);
    int n = (int)__reduce_add_sync(0xffffffffu, (unsigned)th_np);
    if (li == 0) { s_redf[0][wi] = a; s_redf[1][wi] = c; s_redi[wi] = n; }
  }
  __syncthreads();
  float locl = 0.f, pce = 0.f; int npos = 0;
  #pragma unroll
  for (int w = 0; w < NWARP; w++) {
    locl += s_redf[0][w]; pce += s_redf[1][w]; npos += s_redi[w];
  }
  int k = min(3 * npos, NP - npos);

  // ---- Phase C: top-k sum via binary search on float bit patterns ----
  float topk = 0.f;
  if (k > 0) {
    unsigned lo = 0u, hi = 0x7F800000u;
    while (lo < hi) {
      unsigned mid = (lo + hi) >> 1;
      unsigned c = 0;
      #pragma unroll
      for (int i = 0; i < PERF; i++) c += (lcr[i] > mid);
      c = __reduce_add_sync(0xffffffffu, c);
      if (li == 0) s_redi[wi] = (int)c;
      __syncthreads();
      if (wi == 0) {                         // warp0 combines 16 partials
        int t = (li < NWARP) ? s_redi[li] : 0;
        t = (int)__reduce_add_sync(0xffffffffu, (unsigned)t);
        if (li == 0) s_toti = t;
      }
      __syncthreads();
      if (s_toti < k) hi = mid; else lo = mid + 1u;  // uniform across block
    }
    int m = 0; float sg = 0.f;
    #pragma unroll
    for (int i = 0; i < PERF; i++) {
      unsigned u = lcr[i];
      if (u > lo) { m++; sg += __uint_as_float(u); }
    }
    m = (int)__reduce_add_sync(0xffffffffu, (unsigned)m);
    sg = warpSumF(sg);
    if (li == 0) { s_redi[wi] = m; s_redf[2][wi] = sg; }
    __syncthreads();
    if (wi == 0) {
      int mt = (li < NWARP) ? s_redi[li] : 0;
      float st = (li < NWARP) ? s_redf[2][li] : 0.f;
      mt = (int)__reduce_add_sync(0xffffffffu, (unsigned)mt);
      st = warpSumF(st);
      if (li == 0) { s_toti = mt; s_totf = st; }
    }
    __syncthreads();
    topk = s_totf + (float)(k - s_toti) * __uint_as_float(lo);
  }

  // ---- Publish partials; globally-last finalizer writes out ----
  if (tid == 0) {
    g_pl[b] = locl;
    g_pc[b] = pce + topk;
    g_pn[b] = npos;
  }
  __threadfence();
  __syncthreads();
  if (tid == 0) {
    unsigned od = atomicAdd(&g_done, 1u);   // modular: replay-safe
    s_flag2 = ((od % NB) == NB - 1);
  }
  __syncthreads();
  if (s_flag2) {
    __threadfence();
    float L = 0.f, C = 0.f; int n = 0;
    if (tid < NB) {
      L = ((volatile float*)g_pl)[tid];
      C = ((volatile float*)g_pc)[tid];
      n = ((volatile int*)g_pn)[tid];
    }
    L = warpSumF(L); C = warpSumF(C);
    n = (int)__reduce_add_sync(0xffffffffu, (unsigned)n);
    if (li == 0) { s_redf[0][wi] = L; s_redf[1][wi] = C; s_redi[wi] = n; }
    __syncthreads();
    if (tid == 0) {
      float Lt = 0.f, Ct = 0.f; int nt = 0;
      #pragma unroll
      for (int w = 0; w < NWARP; w++) {
        Lt += s_redf[0][w]; Ct += s_redf[1][w]; nt += s_redi[w];
      }
      out[0] = (Lt + Ct) / (float)max(nt, 1);
    }
  }
}

extern "C" void kernel_launch(void* const* d_in, const int* in_sizes, int n_in,
                              void* d_out, int out_size) {
  const float* loc  = (const float*)d_in[0];
  const float* conf = (const float*)d_in[1];
  const float* dbox = (const float*)d_in[2];
  const float* gtb  = (const float*)d_in[3];
  const int*   gtl  = (const int*)d_in[4];
  float* out = (float*)d_out;

  ssd_kernel<<<NB * NT_TOT, TPB>>>(loc, conf, dbox, gtb, gtl, out);
}

// round 10
// speedup vs baseline: 1.5672x; 1.1976x over previous
#include <cuda_runtime.h>
#include <math.h>

#define NP 8732
#define NG 20
#define NC 21
#define NB 128
#define TPB 512
#define NT_L 18            // lse tiles of 512 priors (17*512 + 28)
#define NT_M 6             // match tiles per batch
#define CH 3               // priors per thread (register-resident)
#define MBP (TPB*CH)       // 1536 priors per match block (6*1536 >= 8732)
#define PERF 18            // finalize: ceil(8732/512)
#define NWARP 16

__device__ float g_ce0[(size_t)NB * NP];            // lse - conf[...,0]
__device__ uint2 g_m[(size_t)NB * NP];              // .x = iou bits, .y = best GT
__device__ unsigned long long g_bestp[NB * NG];     // packed (iou_bits<<32)|~p
__device__ float g_pl[NB], g_pc[NB];
__device__ int g_pn[NB];
__device__ unsigned g_done;

__device__ __forceinline__ float warpSumF(float v) {
  #pragma unroll
  for (int o = 16; o > 0; o >>= 1) v += __shfl_down_sync(0xffffffffu, v, o);
  return v;
}
__device__ __forceinline__ float sl1(float x) {
  float a = fabsf(x);
  return a < 1.f ? 0.5f * x * x : a - 0.5f;
}

// ================= Kernel 1: pure DRAM streamer for logsumexp ==============
__global__ void __launch_bounds__(TPB)
lse_kernel(const float* __restrict__ conf) {
  __shared__ float tile[TPB * NC];          // 43008 B
  const int r = blockIdx.x, b = blockIdx.y;
  const int p0  = r * TPB;
  const int cnt = min(TPB, NP - p0);
  const int nf4 = cnt * NC / 4;             // 512*21, 28*21 both %4==0
  const size_t bofs = (size_t)b * NP;
  const float4* src = (const float4*)(conf + (bofs + p0) * NC);
  float4* dst = (float4*)tile;
  for (int i = threadIdx.x; i < nf4; i += TPB) dst[i] = src[i];
  __syncthreads();
  const int x = threadIdx.x;
  if (x < cnt) {
    const float* row = tile + x * NC;       // stride 21: conflict-free
    float s0 = 0.f, s1 = 0.f, s2 = 0.f;
    #pragma unroll
    for (int k = 0; k < 21; k += 3) {
      s0 += __expf(row[k]);
      s1 += __expf(row[k + 1]);
      s2 += __expf(row[k + 2]);
    }
    g_ce0[bofs + p0 + x] = __logf(s0 + s1 + s2) - row[0];
  }
}

// ================= Kernel 2: IoU matching (compute-bound) ==================
__global__ void __launch_bounds__(TPB, 2)
match_kernel(const float* __restrict__ dbox, const float* __restrict__ gtb) {
  __shared__ float4 sg4[NG];
  __shared__ float sga[NG];
  const int bid = blockIdx.x;
  const int b   = bid / NT_M;
  const int mb  = bid - b * NT_M;
  const int tid = threadIdx.x;
  const int li  = tid & 31;
  const size_t bofs = (size_t)b * NP;
  const int mbase = mb * MBP;

  if (tid < NG) {
    float4 g = ((const float4*)gtb)[b * NG + tid];
    sg4[tid] = g;
    sga[tid] = (g.z - g.x) * (g.w - g.y);
  }
  __syncthreads();

  // CH priors fully register-resident
  float ax0[CH], ay0[CH], ax1[CH], ay1[CH], areaA[CH];
  unsigned pidx[CH]; bool valid[CH];
  #pragma unroll
  for (int i = 0; i < CH; i++) {
    int plin = mbase + i * TPB + tid;
    valid[i] = plin < NP;
    pidx[i]  = (unsigned)plin;
    float4 d = ((const float4*)dbox)[min(plin, NP - 1)];   // cx,cy,w,h
    ax0[i] = fmaf(-0.5f, d.z, d.x); ax1[i] = fmaf(0.5f, d.z, d.x);
    ay0[i] = fmaf(-0.5f, d.w, d.y); ay1[i] = fmaf(0.5f, d.w, d.y);
    areaA[i] = d.z * d.w;
  }
  unsigned bb[CH]; int bi[CH];
  #pragma unroll
  for (int i = 0; i < CH; i++) { bb[i] = 0u; bi[i] = 0; }  // zeros -> idx 0

  unsigned long long acc = 0ull;            // lane j holds pk for GT j
  #pragma unroll
  for (int j = 0; j < NG; j++) {
    float4 g = sg4[j];                      // LDS broadcast
    float ga = sga[j];
    unsigned tbits = 0u, tp = 0xFFFFFFFFu;  // thread-local argmax for GT j
    #pragma unroll
    for (int i = 0; i < CH; i++) {
      float w = fminf(ax1[i], g.z) - fmaxf(ax0[i], g.x);
      float h = fminf(ay1[i], g.w) - fmaxf(ay0[i], g.y);
      float inter = fmaxf(w, 0.f) * fmaxf(h, 0.f);
      float iou = __fdividef(inter, (areaA[i] + ga) - inter);
      unsigned bits = __float_as_uint(iou); // iou>=0: order-preserving
      bool gq = bits > bb[i];               // strict >: FIRST max (axis=1)
      bb[i] = gq ? bits : bb[i];
      bi[i] = gq ? j : bi[i];
      unsigned cb = valid[i] ? bits : 0u;
      bool tq = cb > tbits;                 // strict >: lowest i = lowest p
      tbits = tq ? cb : tbits;
      tp    = tq ? pidx[i] : tp;            // tp sentinel iff tbits==0
    }
    // axis=0 argmax across warp: 2 collectives per (warp, GT)
    unsigned mx = __reduce_max_sync(0xffffffffu, tbits);
    unsigned pc = (tbits == mx) ? tp : 0xFFFFFFFFu;
    unsigned pmin = __reduce_min_sync(0xffffffffu, pc);    // smallest p wins
    unsigned long long pk = ((unsigned long long)mx << 32)
                          | (0xFFFFFFFFu - pmin);          // mx==0 -> pk==0
    acc = (li == j) ? pk : acc;
  }
  if (li < NG) atomicMax(&g_bestp[b * NG + li], acc);      // merge blocks
  #pragma unroll
  for (int i = 0; i < CH; i++) {
    if (valid[i]) g_m[bofs + pidx[i]] = make_uint2(bb[i], (unsigned)bi[i]);
  }
}

// ================= Kernel 3: forced matches + losses + top-k ===============
__global__ void __launch_bounds__(TPB, 1)
finalize_kernel(const float* __restrict__ loc, const float* __restrict__ conf,
                const float* __restrict__ dbox, const float* __restrict__ gtb,
                const int* __restrict__ gtl, float* __restrict__ out)
{
  __shared__ float4 sg4[NG];
  __shared__ int sglab[NG];
  __shared__ unsigned sfp[NG];
  __shared__ int s_redi[NWARP];
  __shared__ float s_redf[3][NWARP];
  __shared__ int s_toti, s_flag2; __shared__ float s_totf;

  const int b   = blockIdx.x;
  const int tid = threadIdx.x;
  const int wi  = tid >> 5, li = tid & 31;
  const size_t bofs = (size_t)b * NP;

  if (tid < NG) {
    float4 g = ((const float4*)gtb)[b * NG + tid];
    sg4[tid]   = g;
    sglab[tid] = gtl[b * NG + tid];
    unsigned long long bp = g_bestp[b * NG + tid];
    // bp==0 (GT overlapped nothing): argmax-of-zeros -> prior 0 (JAX)
    sfp[tid] = bp ? (0xFFFFFFFFu - (unsigned)(bp & 0xFFFFFFFFull)) : 0u;
  }
  __syncthreads();
  // Forced matches: sequential last-write-wins (JAX scatter order);
  // same-block gmem coherence via write-through L1 + __syncthreads.
  if (tid == 0) {
    #pragma unroll
    for (int j = 0; j < NG; j++)
      g_m[bofs + sfp[j]] = make_uint2(__float_as_uint(2.f), (unsigned)j);
  }
  __syncthreads();

  // ---- losses; loss_c in registers (no reg cap here: stays resident) ----
  float th_loc = 0.f, th_pce = 0.f; int th_np = 0;
  unsigned lcr[PERF];
  #pragma unroll
  for (int i = 0; i < PERF; i++) {
    int p = tid + i * TPB;
    unsigned v = 0u;
    if (p < NP) {
      uint2 mrec = g_m[bofs + p];
      float biou = __uint_as_float(mrec.x);
      int j = (int)mrec.y;
      float ce0 = g_ce0[bofs + p];
      if (biou > 0.5f) {                    // pos (gt labels all >= 1)
        int lab = sglab[j];
        const float* cp = conf + (bofs + p) * NC;
        float c0 = __ldg(cp), cl = __ldg(cp + lab);
        th_pce += ce0 + c0 - cl;            // ce = lse - conf[lab]
        th_np++;
        float4 d = ((const float4*)dbox)[p];
        float4 g = sg4[j];
        float e0 = ((g.x + g.z) * 0.5f - d.x) / (0.1f * d.z);
        float e1 = ((g.y + g.w) * 0.5f - d.y) / (0.1f * d.w);
        float e2 = __logf((g.z - g.x) / d.z) * 5.f;
        float e3 = __logf((g.w - g.y) / d.w) * 5.f;
        float4 L = ((const float4*)loc)[bofs + p];
        th_loc += sl1(L.x - e0) + sl1(L.y - e1) + sl1(L.z - e2) + sl1(L.w - e3);
      } else {
        v = __float_as_uint(ce0);           // ce0 > 0: bits order-preserving
      }
    }
    lcr[i] = v;
  }

  {
    float a = warpSumF(th_loc), c = warpSumF(th_pce);
    int n = (int)__reduce_add_sync(0xffffffffu, (unsigned)th_np);
    if (li == 0) { s_redf[0][wi] = a; s_redf[1][wi] = c; s_redi[wi] = n; }
  }
  __syncthreads();
  float locl = 0.f, pce = 0.f; int npos = 0;
  #pragma unroll
  for (int w = 0; w < NWARP; w++) {
    locl += s_redf[0][w]; pce += s_redf[1][w]; npos += s_redi[w];
  }
  int k = min(3 * npos, NP - npos);

  // ---- top-k sum via binary search on float bit patterns ----
  float topk = 0.f;
  if (k > 0) {
    unsigned lo = 0u, hi = 0x7F800000u;
    while (lo < hi) {
      unsigned mid = (lo + hi) >> 1;
      unsigned c = 0;
      #pragma unroll
      for (int i = 0; i < PERF; i++) c += (lcr[i] > mid);
      c = __reduce_add_sync(0xffffffffu, c);
      if (li == 0) s_redi[wi] = (int)c;
      __syncthreads();
      if (wi == 0) {                        // warp0 combines 16 partials
        int t = (li < NWARP) ? s_redi[li] : 0;
        t = (int)__reduce_add_sync(0xffffffffu, (unsigned)t);
        if (li == 0) s_toti = t;
      }
      __syncthreads();
      if (s_toti < k) hi = mid; else lo = mid + 1u;  // uniform across block
    }
    int m = 0; float sg = 0.f;
    #pragma unroll
    for (int i = 0; i < PERF; i++) {
      unsigned u = lcr[i];
      if (u > lo) { m++; sg += __uint_as_float(u); }
    }
    m = (int)__reduce_add_sync(0xffffffffu, (unsigned)m);
    sg = warpSumF(sg);
    if (li == 0) { s_redi[wi] = m; s_redf[2][wi] = sg; }
    __syncthreads();
    if (wi == 0) {
      int mt = (li < NWARP) ? s_redi[li] : 0;
      float st = (li < NWARP) ? s_redf[2][li] : 0.f;
      mt = (int)__reduce_add_sync(0xffffffffu, (unsigned)mt);
      st = warpSumF(st);
      if (li == 0) { s_toti = mt; s_totf = st; }
    }
    __syncthreads();
    topk = s_totf + (float)(k - s_toti) * __uint_as_float(lo);
  }

  // ---- Publish partials; globally-last block writes out ----
  if (tid == 0) {
    g_pl[b] = locl;
    g_pc[b] = pce + topk;
    g_pn[b] = npos;
  }
  __threadfence();
  __syncthreads();
  if (tid == 0) {
    unsigned od = atomicAdd(&g_done, 1u);   // modular: replay-safe
    s_flag2 = ((od % NB) == NB - 1);
  }
  __syncthreads();
  if (s_flag2) {
    __threadfence();
    float L = 0.f, C = 0.f; int n = 0;
    if (tid < NB) {
      L = ((volatile float*)g_pl)[tid];
      C = ((volatile float*)g_pc)[tid];
      n = ((volatile int*)g_pn)[tid];
    }
    L = warpSumF(L); C = warpSumF(C);
    n = (int)__reduce_add_sync(0xffffffffu, (unsigned)n);
    if (li == 0) { s_redf[0][wi] = L; s_redf[1][wi] = C; s_redi[wi] = n; }
    __syncthreads();
    if (tid == 0) {
      float Lt = 0.f, Ct = 0.f; int nt = 0;
      #pragma unroll
      for (int w = 0; w < NWARP; w++) {
        Lt += s_redf[0][w]; Ct += s_redf[1][w]; nt += s_redi[w];
      }
      out[0] = (Lt + Ct) / (float)max(nt, 1);
    }
  }
}

extern "C" void kernel_launch(void* const* d_in, const int* in_sizes, int n_in,
                              void* d_out, int out_size) {
  const float* loc  = (const float*)d_in[0];
  const float* conf = (const float*)d_in[1];
  const float* dbox = (const float*)d_in[2];
  const float* gtb  = (const float*)d_in[3];
  const int*   gtl  = (const int*)d_in[4];
  float* out = (float*)d_out;

  lse_kernel<<<dim3(NT_L, NB), TPB>>>(conf);
  match_kernel<<<NB * NT_M, TPB>>>(dbox, gtb);
  finalize_kernel<<<NB, TPB>>>(loc, conf, dbox, gtb, gtl, out);
}

// round 11
// speedup vs baseline: 1.5683x; 1.0007x over previous
#include <cuda_runtime.h>
#include <math.h>

#define NP 8732
#define NG 20
#define NC 21
#define NB 128
#define TPB 512
#define NT_L 18            // lse tiles of 512 priors (17*512 + 28)
#define NT_M 6             // match tiles per batch
#define CH 3               // priors per thread (register-resident)
#define MBP (TPB*CH)       // 1536 priors per match block (6*1536 >= 8732)
#define PERF 18            // finalize: ceil(8732/512)
#define NWARP 16

__device__ float g_ce0[(size_t)NB * NP];            // lse - conf[...,0]
__device__ uint2 g_m[(size_t)NB * NP];              // .x = iou bits, .y = best GT
__device__ unsigned long long g_bestp[NB * NG];     // packed (iou_bits<<32)|~p
__device__ float g_pl[NB], g_pc[NB];
__device__ int g_pn[NB];
__device__ unsigned g_done;

__device__ __forceinline__ float warpSumF(float v) {
  #pragma unroll
  for (int o = 16; o > 0; o >>= 1) v += __shfl_down_sync(0xffffffffu, v, o);
  return v;
}
__device__ __forceinline__ float sl1(float x) {
  float a = fabsf(x);
  return a < 1.f ? 0.5f * x * x : a - 0.5f;
}

// ================= Kernel 1: pure DRAM streamer for logsumexp ==============
__global__ void __launch_bounds__(TPB)
lse_kernel(const float* __restrict__ conf) {
  __shared__ float tile[TPB * NC];          // 43008 B
  const int r = blockIdx.x, b = blockIdx.y;
  const int p0  = r * TPB;
  const int cnt = min(TPB, NP - p0);
  const int nf4 = cnt * NC / 4;             // 512*21, 28*21 both %4==0
  const size_t bofs = (size_t)b * NP;
  const float4* src = (const float4*)(conf + (bofs + p0) * NC);
  float4* dst = (float4*)tile;
  for (int i = threadIdx.x; i < nf4; i += TPB) dst[i] = src[i];
  __syncthreads();
  const int x = threadIdx.x;
  if (x < cnt) {
    const float* row = tile + x * NC;       // stride 21: conflict-free
    float s0 = 0.f, s1 = 0.f, s2 = 0.f;
    #pragma unroll
    for (int k = 0; k < 21; k += 3) {
      s0 += __expf(row[k]);
      s1 += __expf(row[k + 1]);
      s2 += __expf(row[k + 2]);
    }
    g_ce0[bofs + p0 + x] = __logf(s0 + s1 + s2) - row[0];
  }
}

// ================= Kernel 2: IoU matching (compute-bound) ==================
__global__ void __launch_bounds__(TPB, 2)
match_kernel(const float* __restrict__ dbox, const float* __restrict__ gtb) {
  __shared__ float4 sg4[NG];
  __shared__ float sga[NG];
  const int bid = blockIdx.x;
  const int b   = bid / NT_M;
  const int mb  = bid - b * NT_M;
  const int tid = threadIdx.x;
  const int li  = tid & 31;
  const size_t bofs = (size_t)b * NP;
  const int mbase = mb * MBP;

  if (tid < NG) {
    float4 g = ((const float4*)gtb)[b * NG + tid];
    sg4[tid] = g;
    sga[tid] = (g.z - g.x) * (g.w - g.y);
  }
  __syncthreads();

  // CH priors fully register-resident
  float ax0[CH], ay0[CH], ax1[CH], ay1[CH], areaA[CH];
  unsigned pidx[CH]; bool valid[CH];
  #pragma unroll
  for (int i = 0; i < CH; i++) {
    int plin = mbase + i * TPB + tid;
    valid[i] = plin < NP;
    pidx[i]  = (unsigned)plin;
    float4 d = ((const float4*)dbox)[min(plin, NP - 1)];   // cx,cy,w,h
    ax0[i] = fmaf(-0.5f, d.z, d.x); ax1[i] = fmaf(0.5f, d.z, d.x);
    ay0[i] = fmaf(-0.5f, d.w, d.y); ay1[i] = fmaf(0.5f, d.w, d.y);
    areaA[i] = d.z * d.w;
  }
  unsigned bb[CH]; int bi[CH];
  #pragma unroll
  for (int i = 0; i < CH; i++) { bb[i] = 0u; bi[i] = 0; }  // zeros -> idx 0

  unsigned long long acc = 0ull;            // lane j holds pk for GT j
  #pragma unroll
  for (int j = 0; j < NG; j++) {
    float4 g = sg4[j];                      // LDS broadcast
    float ga = sga[j];
    unsigned tbits = 0u, tp = 0xFFFFFFFFu;  // thread-local argmax for GT j
    #pragma unroll
    for (int i = 0; i < CH; i++) {
      float w = fminf(ax1[i], g.z) - fmaxf(ax0[i], g.x);
      float h = fminf(ay1[i], g.w) - fmaxf(ay0[i], g.y);
      float inter = fmaxf(w, 0.f) * fmaxf(h, 0.f);
      float iou = __fdividef(inter, (areaA[i] + ga) - inter);
      unsigned bits = __float_as_uint(iou); // iou>=0: order-preserving
      bool gq = bits > bb[i];               // strict >: FIRST max (axis=1)
      bb[i] = gq ? bits : bb[i];
      bi[i] = gq ? j : bi[i];
      unsigned cb = valid[i] ? bits : 0u;
      bool tq = cb > tbits;                 // strict >: lowest i = lowest p
      tbits = tq ? cb : tbits;
      tp    = tq ? pidx[i] : tp;            // tp sentinel iff tbits==0
    }
    // axis=0 argmax across warp: 2 collectives per (warp, GT)
    unsigned mx = __reduce_max_sync(0xffffffffu, tbits);
    unsigned pc = (tbits == mx) ? tp : 0xFFFFFFFFu;
    unsigned pmin = __reduce_min_sync(0xffffffffu, pc);    // smallest p wins
    unsigned long long pk = ((unsigned long long)mx << 32)
                          | (0xFFFFFFFFu - pmin);          // mx==0 -> pk==0
    acc = (li == j) ? pk : acc;
  }
  if (li < NG) atomicMax(&g_bestp[b * NG + li], acc);      // merge blocks
  #pragma unroll
  for (int i = 0; i < CH; i++) {
    if (valid[i]) g_m[bofs + pidx[i]] = make_uint2(bb[i], (unsigned)bi[i]);
  }
}

// ================= Kernel 3: forced matches + losses + top-k ===============
__global__ void __launch_bounds__(TPB, 1)
finalize_kernel(const float* __restrict__ loc, const float* __restrict__ conf,
                const float* __restrict__ dbox, const float* __restrict__ gtb,
                const int* __restrict__ gtl, float* __restrict__ out)
{
  __shared__ float4 sg4[NG];
  __shared__ int sglab[NG];
  __shared__ unsigned sfp[NG];
  __shared__ int s_redi[NWARP];
  __shared__ float s_redf[3][NWARP];
  __shared__ int s_toti, s_flag2; __shared__ float s_totf;

  const int b   = blockIdx.x;
  const int tid = threadIdx.x;
  const int wi  = tid >> 5, li = tid & 31;
  const size_t bofs = (size_t)b * NP;

  if (tid < NG) {
    float4 g = ((const float4*)gtb)[b * NG + tid];
    sg4[tid]   = g;
    sglab[tid] = gtl[b * NG + tid];
    unsigned long long bp = g_bestp[b * NG + tid];
    // bp==0 (GT overlapped nothing): argmax-of-zeros -> prior 0 (JAX)
    sfp[tid] = bp ? (0xFFFFFFFFu - (unsigned)(bp & 0xFFFFFFFFull)) : 0u;
  }
  __syncthreads();
  // Forced matches: sequential last-write-wins (JAX scatter order);
  // same-block gmem coherence via write-through L1 + __syncthreads.
  if (tid == 0) {
    #pragma unroll
    for (int j = 0; j < NG; j++)
      g_m[bofs + sfp[j]] = make_uint2(__float_as_uint(2.f), (unsigned)j);
  }
  __syncthreads();

  // ---- losses; loss_c in registers (no reg cap here: stays resident) ----
  float th_loc = 0.f, th_pce = 0.f; int th_np = 0;
  unsigned lcr[PERF];
  #pragma unroll
  for (int i = 0; i < PERF; i++) {
    int p = tid + i * TPB;
    unsigned v = 0u;
    if (p < NP) {
      uint2 mrec = g_m[bofs + p];
      float biou = __uint_as_float(mrec.x);
      int j = (int)mrec.y;
      float ce0 = g_ce0[bofs + p];
      if (biou > 0.5f) {                    // pos (gt labels all >= 1)
        int lab = sglab[j];
        const float* cp = conf + (bofs + p) * NC;
        float c0 = __ldg(cp), cl = __ldg(cp + lab);
        th_pce += ce0 + c0 - cl;            // ce = lse - conf[lab]
        th_np++;
        float4 d = ((const float4*)dbox)[p];
        float4 g = sg4[j];
        float e0 = ((g.x + g.z) * 0.5f - d.x) / (0.1f * d.z);
        float e1 = ((g.y + g.w) * 0.5f - d.y) / (0.1f * d.w);
        float e2 = __logf((g.z - g.x) / d.z) * 5.f;
        float e3 = __logf((g.w - g.y) / d.w) * 5.f;
        float4 L = ((const float4*)loc)[bofs + p];
        th_loc += sl1(L.x - e0) + sl1(L.y - e1) + sl1(L.z - e2) + sl1(L.w - e3);
      } else {
        v = __float_as_uint(ce0);           // ce0 > 0: bits order-preserving
      }
    }
    lcr[i] = v;
  }

  {
    float a = warpSumF(th_loc), c = warpSumF(th_pce);
    int n = (int)__reduce_add_sync(0xffffffffu, (unsigned)th_np);
    if (li == 0) { s_redf[0][wi] = a; s_redf[1][wi] = c; s_redi[wi] = n; }
  }
  __syncthreads();
  float locl = 0.f, pce = 0.f; int npos = 0;
  #pragma unroll
  for (int w = 0; w < NWARP; w++) {
    locl += s_redf[0][w]; pce += s_redf[1][w]; npos += s_redi[w];
  }
  int k = min(3 * npos, NP - npos);

  // ---- top-k sum via binary search on float bit patterns ----
  float topk = 0.f;
  if (k > 0) {
    unsigned lo = 0u, hi = 0x7F800000u;
    while (lo < hi) {
      unsigned mid = (lo + hi) >> 1;
      unsigned c = 0;
      #pragma unroll
      for (int i = 0; i < PERF; i++) c += (lcr[i] > mid);
      c = __reduce_add_sync(0xffffffffu, c);
      if (li == 0) s_redi[wi] = (int)c;
      __syncthreads();
      if (wi == 0) {                        // warp0 combines 16 partials
        int t = (li < NWARP) ? s_redi[li] : 0;
        t = (int)__reduce_add_sync(0xffffffffu, (unsigned)t);
        if (li == 0) s_toti = t;
      }
      __syncthreads();
      if (s_toti < k) hi = mid; else lo = mid + 1u;  // uniform across block
    }
    int m = 0; float sg = 0.f;
    #pragma unroll
    for (int i = 0; i < PERF; i++) {
      unsigned u = lcr[i];
      if (u > lo) { m++; sg += __uint_as_float(u); }
    }
    m = (int)__reduce_add_sync(0xffffffffu, (unsigned)m);
    sg = warpSumF(sg);
    if (li == 0) { s_redi[wi] = m; s_redf[2][wi] = sg; }
    __syncthreads();
    if (wi == 0) {
      int mt = (li < NWARP) ? s_redi[li] : 0;
      float st = (li < NWARP) ? s_redf[2][li] : 0.f;
      mt = (int)__reduce_add_sync(0xffffffffu, (unsigned)mt);
      st = warpSumF(st);
      if (li == 0) { s_toti = mt; s_totf = st; }
    }
    __syncthreads();
    topk = s_totf + (float)(k - s_toti) * __uint_as_float(lo);
  }

  // ---- Publish partials; globally-last block writes out ----
  if (tid == 0) {
    g_pl[b] = locl;
    g_pc[b] = pce + topk;
    g_pn[b] = npos;
  }
  __threadfence();
  __syncthreads();
  if (tid == 0) {
    unsigned od = atomicAdd(&g_done, 1u);   // modular: replay-safe
    s_flag2 = ((od % NB) == NB - 1);
  }
  __syncthreads();
  if (s_flag2) {
    __threadfence();
    float L = 0.f, C = 0.f; int n = 0;
    if (tid < NB) {
      L = ((volatile float*)g_pl)[tid];
      C = ((volatile float*)g_pc)[tid];
      n = ((volatile int*)g_pn)[tid];
    }
    L = warpSumF(L); C = warpSumF(C);
    n = (int)__reduce_add_sync(0xffffffffu, (unsigned)n);
    if (li == 0) { s_redf[0][wi] = L; s_redf[1][wi] = C; s_redi[wi] = n; }
    __syncthreads();
    if (tid == 0) {
      float Lt = 0.f, Ct = 0.f; int nt = 0;
      #pragma unroll
      for (int w = 0; w < NWARP; w++) {
        Lt += s_redf[0][w]; Ct += s_redf[1][w]; nt += s_redi[w];
      }
      out[0] = (Lt + Ct) / (float)max(nt, 1);
    }
  }
}

extern "C" void kernel_launch(void* const* d_in, const int* in_sizes, int n_in,
                              void* d_out, int out_size) {
  const float* loc  = (const float*)d_in[0];
  const float* conf = (const float*)d_in[1];
  const float* dbox = (const float*)d_in[2];
  const float* gtb  = (const float*)d_in[3];
  const int*   gtl  = (const int*)d_in[4];
  float* out = (float*)d_out;

  lse_kernel<<<dim3(NT_L, NB), TPB>>>(conf);
  match_kernel<<<NB * NT_M, TPB>>>(dbox, gtb);
  finalize_kernel<<<NB, TPB>>>(loc, conf, dbox, gtb, gtl, out);
}